// round 9
// baseline (speedup 1.0000x reference)
#include <cuda_runtime.h>
#include <cuda_bf16.h>
#include <cstdint>
#include <math.h>

#define K_DIM 128
#define D_DIM 256
#define TILE_M 128
#define NTHREADS 256
#define DC 64
#define SB 144               // smem row stride bytes (72 bf16): conflict-free ldmatrix
#define ATILE 18432          // 128 * 144
#define STAGE 36864          // A tile + B tile per stage
#define LW 132               // logits smem row stride (f32)

// ---- dynamic smem layout (bytes): two stages, logits aliased over stages ----
#define SMEM_A(s)   ((s) * STAGE)
#define SMEM_B(s)   ((s) * STAGE + ATILE)
#define SMEM_LOGITS 0                    // [128][132] f32 = 67584 B (aliases stages)
#define SMEM_MISC   73728
#define SMEM_C2     (SMEM_MISC + 0)      // 128 f32
#define SMEM_X2     (SMEM_MISC + 512)    // 128 f32
#define SMEM_IDX    (SMEM_MISC + 1024)   // 128 i32
#define SMEM_FCNT   (SMEM_MISC + 1536)
#define SMEM_FLIST  (SMEM_MISC + 1540)   // 128 i32
#define SMEM_SC1    (SMEM_MISC + 2052)   // 256 f32 fallback partials
#define SMEM_SC2    (SMEM_MISC + 3076)   // 128 f32 fallback logits
#define SMEM_TOTAL  (SMEM_MISC + 3600)   // 77328 B -> 2 CTAs/SM

__device__ float g_c2[K_DIM];
// Pre-converted B (bf16), per chunk, padded layout == smem image
__device__ __align__(16) unsigned char g_B[4 * ATILE];

// ---------------- PTX helpers ----------------
__device__ __forceinline__ uint32_t smem_u32(const void* p) {
    uint32_t a;
    asm("{ .reg .u64 t; cvta.to.shared.u64 t, %1; cvt.u32.u64 %0, t; }"
        : "=r"(a) : "l"(p));
    return a;
}
__device__ __forceinline__ void ldsm4(uint32_t* r, uint32_t addr) {
    asm volatile("ldmatrix.sync.aligned.m8n8.x4.shared.b16 {%0,%1,%2,%3}, [%4];"
                 : "=r"(r[0]), "=r"(r[1]), "=r"(r[2]), "=r"(r[3]) : "r"(addr));
}
__device__ __forceinline__ void mma_bf16(float* d, const uint32_t* a, const uint32_t* b) {
    asm volatile("mma.sync.aligned.m16n8k16.row.col.f32.bf16.bf16.f32 "
                 "{%0,%1,%2,%3}, {%4,%5,%6,%7}, {%8,%9}, {%0,%1,%2,%3};"
                 : "+f"(d[0]), "+f"(d[1]), "+f"(d[2]), "+f"(d[3])
                 : "r"(a[0]), "r"(a[1]), "r"(a[2]), "r"(a[3]), "r"(b[0]), "r"(b[1]));
}
__device__ __forceinline__ void cp16(uint32_t smaddr, const void* gaddr) {
    asm volatile("cp.async.ca.shared.global [%0], [%1], 16;"
                 :: "r"(smaddr), "l"(gaddr) : "memory");
}
#define CP_COMMIT() asm volatile("cp.async.commit_group;" ::: "memory")
#define CP_WAIT0()  asm volatile("cp.async.wait_group 0;" ::: "memory")

__device__ __forceinline__ uint32_t pack_bf2(float a, float b) {
    __nv_bfloat16 ha = __float2bfloat16_rn(a), hb = __float2bfloat16_rn(b);
    uint16_t ra = *reinterpret_cast<uint16_t*>(&ha);
    uint16_t rb = *reinterpret_cast<uint16_t*>(&hb);
    return (uint32_t)ra | ((uint32_t)rb << 16);
}

// ---------------- prep (parallel): block b -> c2[b] + 256-elem B slice ----------------
__global__ void prep_kernel(const float* __restrict__ C) {
    __shared__ float red[8];
    const int tid = threadIdx.x;
    const int bid = blockIdx.x;       // 0..127

    // c2[bid] via block reduce over 256 elems
    float v = C[(size_t)bid * D_DIM + tid];
    float s = v * v;
#pragma unroll
    for (int o = 16; o >= 1; o >>= 1) s += __shfl_xor_sync(0xffffffffu, s, o);
    if ((tid & 31) == 0) red[tid >> 5] = s;
    __syncthreads();
    if (tid == 0) {
        float t = 0.f;
#pragma unroll
        for (int w = 0; w < 8; ++w) t += red[w];
        g_c2[bid] = t;
    }

    // B conversion: elem e = bid*256 + tid
    int e = bid * 256 + tid;          // 0..32767
    int ch = e >> 13, r = (e >> 6) & 127, d = e & 63;
    float val = C[(size_t)r * D_DIM + ch * DC + d];
    __nv_bfloat16 h = __float2bfloat16_rn(val);
    *reinterpret_cast<uint16_t*>(&g_B[ch * ATILE + r * SB + d * 2]) =
        *reinterpret_cast<uint16_t*>(&h);
}

// ---------------- main ----------------
__global__ __launch_bounds__(NTHREADS, 2)
void assign_kernel(const float* __restrict__ seq, const float* __restrict__ u,
                   const float* __restrict__ C, float* __restrict__ assign,
                   int N) {
    extern __shared__ char smem[];
    const uint32_t sm = smem_u32(smem);
    const int tid = threadIdx.x;
    const int wid = tid >> 5;
    const int lane = tid & 31;
    const int row0 = blockIdx.x * TILE_M;

    float* c2s = (float*)(smem + SMEM_C2);
    float* x2s = (float*)(smem + SMEM_X2);
    float* lgt = (float*)(smem + SMEM_LOGITS);
    int*   idxs = (int*)(smem + SMEM_IDX);
    int*   fcnt = (int*)(smem + SMEM_FCNT);
    int*   flist = (int*)(smem + SMEM_FLIST);
    float* sc1 = (float*)(smem + SMEM_SC1);
    float* sc2 = (float*)(smem + SMEM_SC2);

    if (tid < K_DIM) c2s[tid] = g_c2[tid];
    if (tid == 0) *fcnt = 0;

    const int wr = wid >> 1;       // 0..3: rows wr*32..+31
    const int wc = wid & 1;        // 0..1: cols wc*64..+63

    float acc[2][8][4];
#pragma unroll
    for (int mi = 0; mi < 2; mi++)
#pragma unroll
        for (int ni = 0; ni < 8; ni++)
#pragma unroll
            for (int j = 0; j < 4; j++) acc[mi][ni][j] = 0.f;

    float4 av[8];

#define LD_A(CH) do {                                                            \
    _Pragma("unroll")                                                            \
    for (int i = 0; i < 8; ++i) {                                                \
        int f = tid + NTHREADS * i;                                              \
        int row = f >> 4, c4 = f & 15, grow = row0 + row;                        \
        av[i] = make_float4(0.f, 0.f, 0.f, 0.f);                                 \
        if (grow < N)                                                            \
            av[i] = *reinterpret_cast<const float4*>(                            \
                seq + (size_t)grow * D_DIM + (CH) * DC + 4 * c4);                \
    }                                                                            \
} while (0)

#define CP_B(CH, S) do {                                                         \
    const unsigned char* src = g_B + (CH) * ATILE;                               \
    uint32_t dst = sm + SMEM_B(S);                                               \
    _Pragma("unroll")                                                            \
    for (int j = 0; j < 5; ++j) {                                                \
        int off = (tid + NTHREADS * j) * 16;                                     \
        if (off < ATILE) cp16(dst + off, src + off);                             \
    }                                                                            \
} while (0)

#define CVT_A(S, FIRST) do {                                                     \
    char* dst = smem + SMEM_A(S);                                                \
    _Pragma("unroll")                                                            \
    for (int i = 0; i < 8; ++i) {                                                \
        int f = tid + NTHREADS * i;                                              \
        int row = f >> 4, c4 = f & 15;                                           \
        float4 v = av[i];                                                        \
        float part = v.x * v.x + v.y * v.y + v.z * v.z + v.w * v.w;              \
        _Pragma("unroll")                                                        \
        for (int o = 8; o >= 1; o >>= 1)                                         \
            part += __shfl_xor_sync(0xffffffffu, part, o);                       \
        if ((lane & 15) == 0) {                                                  \
            if (FIRST) x2s[row] = part; else x2s[row] += part;                   \
        }                                                                        \
        *reinterpret_cast<uint2*>(dst + (uint32_t)row * SB + c4 * 8) =           \
            make_uint2(pack_bf2(v.x, v.y), pack_bf2(v.z, v.w));                  \
    }                                                                            \
} while (0)

    // ---- prologue: stage 0 holds chunk 0 ----
    CP_B(0, 0);
    CP_COMMIT();
    LD_A(0);
    CVT_A(0, true);
    CP_WAIT0();
    __syncthreads();

    // ---- pipelined mainloop: one sync per chunk ----
#pragma unroll
    for (int ch = 0; ch < 4; ++ch) {
        const int cur = ch & 1, nxt = cur ^ 1;
        if (ch < 3) {
            CP_B(ch + 1, nxt);      // other stage: overlaps MMA(cur), no hazard
            CP_COMMIT();
            LD_A(ch + 1);           // DRAM latency hides under MMA
        }
        const uint32_t aBase = sm + SMEM_A(cur);
        const uint32_t bBase = sm + SMEM_B(cur);
#pragma unroll
        for (int ks = 0; ks < 4; ++ks) {
            uint32_t ah[2][4];
            const uint32_t a_lane_off =
                (uint32_t)(lane & 15) * SB + (uint32_t)(lane >> 4) * 16 + (uint32_t)ks * 32;
#pragma unroll
            for (int mi = 0; mi < 2; ++mi)
                ldsm4(ah[mi], aBase + (uint32_t)(wr * 32 + mi * 16) * SB + a_lane_off);
            const uint32_t b_lane_off =
                (uint32_t)((lane & 7) + ((lane >> 4) << 3)) * SB +
                (uint32_t)ks * 32 + (uint32_t)(((lane >> 3) & 1) << 4);
#pragma unroll
            for (int np = 0; np < 4; ++np) {
                uint32_t bh[4];
                ldsm4(bh, bBase + (uint32_t)(wc * 64 + np * 16) * SB + b_lane_off);
#pragma unroll
                for (int mi = 0; mi < 2; ++mi) {
                    mma_bf16(acc[mi][np * 2 + 0], ah[mi], bh + 0);
                    mma_bf16(acc[mi][np * 2 + 1], ah[mi], bh + 2);
                }
            }
        }
        if (ch < 3) {
            CVT_A(nxt, false);      // writes other stage; overlaps in-flight cp.async
            CP_WAIT0();
        }
        __syncthreads();
    }

    // ---- epilogue: dump dots to smem, then coalesced per-row pass ----
    {
        const int g = lane >> 2;
        const int tig = lane & 3;
#pragma unroll
        for (int mi = 0; mi < 2; ++mi) {
#pragma unroll
            for (int half = 0; half < 2; ++half) {
                int row = wr * 32 + mi * 16 + g + 8 * half;
#pragma unroll
                for (int ni = 0; ni < 8; ++ni) {
                    int col = wc * 64 + ni * 8 + tig * 2;
                    *reinterpret_cast<float2*>(&lgt[row * LW + col]) =
                        make_float2(acc[mi][ni][2 * half], acc[mi][ni][2 * half + 1]);
                }
            }
        }
    }
    __syncthreads();

    // one warp per row (16 rows/warp); lanes span 128 cols, 4 each -> coalesced
    for (int r = 0; r < 16; ++r) {
        int row = wid * 16 + r;
        int grow = row0 + row;
        float x2r = x2s[row];
        float4 dots = *reinterpret_cast<const float4*>(&lgt[row * LW + lane * 4]);
        float4 c2v  = *reinterpret_cast<const float4*>(&c2s[lane * 4]);
        float4 uv   = *reinterpret_cast<const float4*>(
            u + (size_t)(grow < N ? grow : 0) * K_DIM + lane * 4);
        float best = -INFINITY, second = -INFINITY;
        int bidx = 0;
#pragma unroll
        for (int q = 0; q < 4; ++q) {
            float dot = (&dots.x)[q];
            float sq = fmaxf(x2r - 2.f * dot + (&c2v.x)[q], 0.f);
            float us = (&uv.x)[q];
            float gb = -__logf(-__logf(us + 1e-10f) + 1e-10f);
            float lg = sqrtf(sq) + gb;
            if (lg > best) { second = best; best = lg; bidx = lane * 4 + q; }
            else if (lg > second) { second = lg; }
        }
#pragma unroll
        for (int o = 1; o <= 16; o <<= 1) {
            float b2 = __shfl_xor_sync(0xffffffffu, best, o);
            float s2 = __shfl_xor_sync(0xffffffffu, second, o);
            int i2 = __shfl_xor_sync(0xffffffffu, bidx, o);
            float lo = fminf(best, b2);
            if (b2 > best || (b2 == best && i2 < bidx)) {
                second = fmaxf(lo, s2); best = b2; bidx = i2;
            } else {
                second = fmaxf(lo, second);
            }
        }
        if (lane == 0) {
            idxs[row] = bidx;
            if (grow < N && best - second < 4e-3f) {
                int p = atomicAdd(fcnt, 1);
                flist[p] = row;
            }
        }
    }
    __syncthreads();

    // ---- exact fp32 fallback for flagged rows (~0.5/CTA) ----
    int nf = *fcnt;
    for (int f = 0; f < nf; ++f) {
        int row = flist[f];
        int grow = row0 + row;
        {
            int k = tid & 127, h = tid >> 7;
            const float* xr = seq + (size_t)grow * D_DIM + h * 128;
            const float* cr = C + (size_t)k * D_DIM + h * 128;
            float p = 0.f;
#pragma unroll 8
            for (int d = 0; d < 128; ++d) p = fmaf(xr[d], cr[d], p);
            sc1[tid] = p;
        }
        __syncthreads();
        if (tid < 128) {
            float dot = sc1[tid] + sc1[tid + 128];
            float sq = fmaxf(x2s[row] - 2.f * dot + c2s[tid], 0.f);
            float us = u[(size_t)grow * K_DIM + tid];
            sc2[tid] = sqrtf(sq) - logf(-logf(us + 1e-10f) + 1e-10f);
        }
        __syncthreads();
        if (tid == 0) {
            float bv = -INFINITY; int bi = 0;
            for (int k = 0; k < K_DIM; ++k)
                if (sc2[k] > bv) { bv = sc2[k]; bi = k; }
            idxs[row] = bi;
        }
        __syncthreads();
    }

    // ---- coalesced one-hot store ----
#pragma unroll
    for (int it = 0; it < 16; ++it) {
        int item = tid + NTHREADS * it;   // 0..4095
        int row = item >> 5;
        int c4 = item & 31;
        int grow = row0 + row;
        if (grow < N) {
            int hot = idxs[row];
            float4 o = make_float4(0.f, 0.f, 0.f, 0.f);
            if ((hot >> 2) == c4) reinterpret_cast<float*>(&o)[hot & 3] = 1.0f;
            *reinterpret_cast<float4*>(assign + (size_t)grow * K_DIM + 4 * c4) = o;
        }
    }
}

extern "C" void kernel_launch(void* const* d_in, const int* in_sizes, int n_in,
                              void* d_out, int out_size) {
    const float* seq = (const float*)d_in[0];  // [N,256]
    const float* u   = (const float*)d_in[1];  // [N,128]
    const float* C   = (const float*)d_in[2];  // [128,256]

    const int N = in_sizes[1] / K_DIM;
    float* out = (float*)d_out;
    float* assign = out;

    long long need_both = (long long)N * K_DIM + (long long)K_DIM * D_DIM;
    if ((long long)out_size >= need_both) {
        cudaMemcpyAsync(out, C, (size_t)K_DIM * D_DIM * sizeof(float),
                        cudaMemcpyDeviceToDevice);
        assign = out + K_DIM * D_DIM;
    }

    prep_kernel<<<128, 256>>>(C);

    cudaFuncSetAttribute(assign_kernel,
                         cudaFuncAttributeMaxDynamicSharedMemorySize, SMEM_TOTAL);
    int grid = (N + TILE_M - 1) / TILE_M;
    assign_kernel<<<grid, NTHREADS, SMEM_TOTAL>>>(seq, u, C, assign, N);
}